// round 2
// baseline (speedup 1.0000x reference)
#include <cuda_runtime.h>
#include <cuda_bf16.h>
#include <cstdint>

// Problem constants
#define NNODES 100000
#define NEDGES 500000
#define DZ     128
#define HID    512
#define NCOLS  1024     // [A | B] per node
#define OUTC   2

// Scratch: C[n][0:512] = A = z@W1a^T + b1 ; C[n][512:1024] = B = z@W1b^T
__device__ float g_C[(size_t)NNODES * NCOLS];
// Wt[k][j]: j<512 -> W1[j][k]; j>=512 -> W1[j-512][k+128]
__device__ float g_Wt[DZ * NCOLS];

// ---------------------------------------------------------------------------
// Kernel 1: build Wt (tiny)
// ---------------------------------------------------------------------------
__global__ void build_wt_kernel(const float* __restrict__ W1) {
    int idx = blockIdx.x * blockDim.x + threadIdx.x;
    if (idx >= DZ * NCOLS) return;
    int k = idx / NCOLS;
    int j = idx % NCOLS;
    float v;
    if (j < HID) v = W1[(size_t)j * 256 + k];
    else         v = W1[(size_t)(j - HID) * 256 + (k + 128)];
    g_Wt[idx] = v;
}

// ---------------------------------------------------------------------------
// Kernel 2: C[M,1024] = z[M,128] @ Wt[128,1024]  (+ b1 on first 512 cols)
// Classic 128x128 tile SGEMM, BK=16, 256 threads, 8x8 per-thread microtile.
// ---------------------------------------------------------------------------
#define BM 128
#define BN 128
#define BK 16
#define TM 8
#define TN 8

__global__ __launch_bounds__(256)
void precompute_gemm_kernel(const float* __restrict__ z,
                            const float* __restrict__ b1) {
    __shared__ float As[BK][BM + 4];   // transposed A tile (pad vs store conflicts)
    __shared__ float Bs[BK][BN];

    const int bm = blockIdx.x * BM;    // M offset
    const int bn = blockIdx.y * BN;    // N offset (0..7 tiles)
    const int tid = threadIdx.x;

    const int tx = tid & 15;           // N direction (16 threads * TN=8 -> 128)
    const int ty = tid >> 4;           // M direction (16 threads * TM=8 -> 128)

    // A-tile global load mapping: float4 along K
    const int lr = tid >> 2;           // 0..63 (row within tile, pass adds 64)
    const int lk = (tid & 3) * 4;      // K offset within BK: 0,4,8,12
    // B-tile global load mapping: float4 along N
    const int brow = tid >> 5;         // 0..7 (k row, pass adds 8)
    const int bcol = (tid & 31) * 4;   // 0..124

    float acc[TM][TN];
    #pragma unroll
    for (int i = 0; i < TM; i++)
        #pragma unroll
        for (int j = 0; j < TN; j++) acc[i][j] = 0.0f;

    for (int k0 = 0; k0 < DZ; k0 += BK) {
        // Load A tile (z), transposed into As[k][m]
        #pragma unroll
        for (int p = 0; p < 2; p++) {
            int row = lr + p * 64;
            int gr = bm + row;
            float4 v = make_float4(0.f, 0.f, 0.f, 0.f);
            if (gr < NNODES)
                v = *(const float4*)(z + (size_t)gr * DZ + k0 + lk);
            As[lk + 0][row] = v.x;
            As[lk + 1][row] = v.y;
            As[lk + 2][row] = v.z;
            As[lk + 3][row] = v.w;
        }
        // Load B tile (Wt)
        #pragma unroll
        for (int p = 0; p < 2; p++) {
            int row = brow + p * 8;
            *(float4*)(&Bs[row][bcol]) =
                *(const float4*)(g_Wt + (size_t)(k0 + row) * NCOLS + bn + bcol);
        }
        __syncthreads();

        #pragma unroll
        for (int k = 0; k < BK; k++) {
            float a[TM], b[TN];
            #pragma unroll
            for (int i = 0; i < TM; i += 4)
                *(float4*)(&a[i]) = *(const float4*)(&As[k][ty * TM + i]);
            #pragma unroll
            for (int j = 0; j < TN; j += 4)
                *(float4*)(&b[j]) = *(const float4*)(&Bs[k][tx * TN + j]);
            #pragma unroll
            for (int i = 0; i < TM; i++)
                #pragma unroll
                for (int j = 0; j < TN; j++)
                    acc[i][j] = fmaf(a[i], b[j], acc[i][j]);
        }
        __syncthreads();
    }

    // Epilogue: add b1 to first 512 cols, store
    #pragma unroll
    for (int i = 0; i < TM; i++) {
        int row = bm + ty * TM + i;
        if (row >= NNODES) continue;
        #pragma unroll
        for (int j = 0; j < TN; j += 4) {
            int col = bn + tx * TN + j;
            float4 v;
            v.x = acc[i][j + 0];
            v.y = acc[i][j + 1];
            v.z = acc[i][j + 2];
            v.w = acc[i][j + 3];
            if (col < HID) {   // whole float4 is on one side (HID%4==0, col%4==0)
                v.x += b1[col + 0];
                v.y += b1[col + 1];
                v.z += b1[col + 2];
                v.w += b1[col + 3];
            }
            *(float4*)(g_C + (size_t)row * NCOLS + col) = v;
        }
    }
}

// ---------------------------------------------------------------------------
// Kernel 3: per-edge fused relu + tiny GEMM (OUT=2).
// One warp per edge. Reads A[r] (2KB) + B[c] (2KB), reduces with W2.
// ---------------------------------------------------------------------------
#define EDGE_WARPS 8

__global__ __launch_bounds__(EDGE_WARPS * 32)
void edge_kernel(const int* __restrict__ batch_r,
                 const int* __restrict__ batch_c,
                 const float* __restrict__ W2,
                 const float* __restrict__ b2,
                 float* __restrict__ out) {
    __shared__ float4 sW0[HID / 4];
    __shared__ float4 sW1[HID / 4];

    const int tid = threadIdx.x;
    if (tid < HID / 4) {
        sW0[tid] = ((const float4*)W2)[tid];
        sW1[tid] = ((const float4*)(W2 + HID))[tid];
    }
    __syncthreads();

    const int warp = tid >> 5;
    const int lane = tid & 31;
    const int e = blockIdx.x * EDGE_WARPS + warp;
    if (e >= NEDGES) return;

    const int r = batch_r[e];
    const int c = batch_c[e];

    const float4* pa = (const float4*)(g_C + (size_t)r * NCOLS);        // A half
    const float4* pb = (const float4*)(g_C + (size_t)c * NCOLS + HID);  // B half

    float s0 = 0.f, s1 = 0.f;
    #pragma unroll
    for (int it = 0; it < 4; it++) {
        int t = lane + it * 32;          // 0..127 float4 index
        float4 a = pa[t];
        float4 b = pb[t];
        float4 w0 = sW0[t];
        float4 w1 = sW1[t];
        float h;
        h = fmaxf(a.x + b.x, 0.f); s0 = fmaf(h, w0.x, s0); s1 = fmaf(h, w1.x, s1);
        h = fmaxf(a.y + b.y, 0.f); s0 = fmaf(h, w0.y, s0); s1 = fmaf(h, w1.y, s1);
        h = fmaxf(a.z + b.z, 0.f); s0 = fmaf(h, w0.z, s0); s1 = fmaf(h, w1.z, s1);
        h = fmaxf(a.w + b.w, 0.f); s0 = fmaf(h, w0.w, s0); s1 = fmaf(h, w1.w, s1);
    }

    // warp reduction
    #pragma unroll
    for (int off = 16; off > 0; off >>= 1) {
        s0 += __shfl_down_sync(0xffffffff, s0, off);
        s1 += __shfl_down_sync(0xffffffff, s1, off);
    }

    if (lane == 0) {
        float2 o;
        o.x = s0 + b2[0];
        o.y = s1 + b2[1];
        *(float2*)(out + (size_t)e * OUTC) = o;
    }
}

// ---------------------------------------------------------------------------
// Launch
// ---------------------------------------------------------------------------
extern "C" void kernel_launch(void* const* d_in, const int* in_sizes, int n_in,
                              void* d_out, int out_size) {
    const float* z       = (const float*)d_in[0];
    const int*   batch_r = (const int*)  d_in[1];
    const int*   batch_c = (const int*)  d_in[2];
    const float* W1      = (const float*)d_in[3];
    const float* b1      = (const float*)d_in[4];
    const float* W2      = (const float*)d_in[5];
    const float* b2      = (const float*)d_in[6];
    float* out = (float*)d_out;

    // 1) Wt layout prep
    build_wt_kernel<<<(DZ * NCOLS + 255) / 256, 256>>>(W1);

    // 2) Precompute C = [A|B] (+b1 on A half)
    dim3 ggrid((NNODES + BM - 1) / BM, NCOLS / BN);
    precompute_gemm_kernel<<<ggrid, 256>>>(z, b1);

    // 3) Fused edge decode
    edge_kernel<<<(NEDGES + EDGE_WARPS - 1) / EDGE_WARPS, EDGE_WARPS * 32>>>(
        batch_r, batch_c, W2, b2, out);
}

// round 5
// speedup vs baseline: 1.7539x; 1.7539x over previous
#include <cuda_runtime.h>
#include <cuda_fp16.h>
#include <cuda_bf16.h>
#include <cstdint>

// Problem constants
#define NNODES 100000
#define NEDGES 500000
#define DZ     128
#define HID    512
#define NCOLS  1024     // [A | B] per node
#define OUTC   2
#define KTOT   384      // 3x compensated K: [zh|zh|zl] x [wh|wl|wh]

// Scratch (static device arrays: allocation-free per harness rules)
__device__ __half        g_Ch[(size_t)NNODES * NCOLS];   // C = [A|B] in fp16 (205 MB)
__device__ __nv_bfloat16 g_A[(size_t)NNODES * KTOT];     // A' (77 MB)
__device__ __nv_bfloat16 g_B[(size_t)NCOLS  * KTOT];     // B' (768 KB)

__device__ __forceinline__ uint32_t smem_u32(const void* p) {
    uint32_t a;
    asm("{ .reg .u64 t; cvta.to.shared.u64 t, %1; cvt.u32.u64 %0, t; }"
        : "=r"(a) : "l"(p));
    return a;
}

__device__ __forceinline__ uint2 split_pack(float4 v, uint2& lo_out) {
    // hi = bf16(v), lo = bf16(v - hi)
    uint16_t h[4], l[4];
    float f[4] = {v.x, v.y, v.z, v.w};
    #pragma unroll
    for (int i = 0; i < 4; i++) {
        __nv_bfloat16 hb = __float2bfloat16(f[i]);
        __nv_bfloat16 lb = __float2bfloat16(f[i] - __bfloat162float(hb));
        h[i] = __bfloat16_as_ushort(hb);
        l[i] = __bfloat16_as_ushort(lb);
    }
    uint2 ph, pl;
    ph.x = (uint32_t)h[0] | ((uint32_t)h[1] << 16);
    ph.y = (uint32_t)h[2] | ((uint32_t)h[3] << 16);
    pl.x = (uint32_t)l[0] | ((uint32_t)l[1] << 16);
    pl.y = (uint32_t)l[2] | ((uint32_t)l[3] << 16);
    lo_out = pl;
    return ph;
}

// ---------------------------------------------------------------------------
// Prep A': row m = [zh(128) | zh(128) | zl(128)]
// ---------------------------------------------------------------------------
__global__ __launch_bounds__(256)
void prep_a_kernel(const float* __restrict__ z) {
    int idx = blockIdx.x * blockDim.x + threadIdx.x;   // over NNODES*32 float4s
    if (idx >= NNODES * 32) return;
    int m = idx >> 5;
    int c4 = idx & 31;
    float4 v = __ldg(((const float4*)z) + idx);
    uint2 pl;
    uint2 ph = split_pack(v, pl);
    size_t base = (size_t)m * KTOT + c4 * 4;
    *(uint2*)(g_A + base)       = ph;   // block0: zh
    *(uint2*)(g_A + base + 128) = ph;   // block1: zh
    *(uint2*)(g_A + base + 256) = pl;   // block2: zl
}

// ---------------------------------------------------------------------------
// Prep B': row n (out-col) = [wh(128) | wl(128) | wh(128)]
// n<512: w = W1[n][0:128]; n>=512: w = W1[n-512][128:256]
// ---------------------------------------------------------------------------
__global__ __launch_bounds__(256)
void prep_b_kernel(const float* __restrict__ W1) {
    int idx = blockIdx.x * blockDim.x + threadIdx.x;   // over NCOLS*32
    if (idx >= NCOLS * 32) return;
    int n = idx >> 5;
    int c4 = idx & 31;
    const float4* src = (n < HID)
        ? ((const float4*)W1 + n * 64 + c4)
        : ((const float4*)W1 + (n - HID) * 64 + 32 + c4);
    float4 v = __ldg(src);
    uint2 pl;
    uint2 ph = split_pack(v, pl);
    size_t base = (size_t)n * KTOT + c4 * 4;
    *(uint2*)(g_B + base)       = ph;   // block0: wh
    *(uint2*)(g_B + base + 128) = pl;   // block1: wl
    *(uint2*)(g_B + base + 256) = ph;   // block2: wh
}

// ---------------------------------------------------------------------------
// HMMA GEMM: C[M,1024] = A'[M,384] @ B'[1024,384]^T  (+ b1 on cols < 512),
// stored fp16. Tile 128x128x32, 256 threads (8 warps, each 64x32),
// mma.m16n8k16 bf16, cp.async 2-stage pipeline, ldmatrix operand loads.
// ---------------------------------------------------------------------------
#define BM 128
#define BN 128
#define BK 32
#define LDA 40       // smem row stride in elems (conflict-free for ldmatrix)
#define NIT (KTOT / BK)   // 12

__global__ __launch_bounds__(256, 2)
void gemm_hmma_kernel(const float* __restrict__ b1) {
    __shared__ __nv_bfloat16 As[2][BM][LDA];
    __shared__ __nv_bfloat16 Bs[2][BN][LDA];

    const int tid  = threadIdx.x;
    const int lane = tid & 31;
    const int wid  = tid >> 5;
    const int wm   = wid >> 2;       // 0..1 -> m offset wm*64
    const int wn   = wid & 3;        // 0..3 -> n offset wn*32
    const int bn   = blockIdx.x * BN;   // x = n-tile so concurrent CTAs share A
    const int bm   = blockIdx.y * BM;

    float acc[4][4][4];
    #pragma unroll
    for (int i = 0; i < 4; i++)
        #pragma unroll
        for (int j = 0; j < 4; j++)
            #pragma unroll
            for (int k = 0; k < 4; k++) acc[i][j][k] = 0.0f;

    // per-lane ldmatrix address components
    const int a_r = lane & 15;
    const int a_k = (lane >> 4) * 8;
    const int b_r = (lane & 7) + (lane >> 4) * 8;
    const int b_k = ((lane >> 3) & 1) * 8;

    auto load_stage = [&](int it, int buf) {
        const int k0 = it * BK;
        #pragma unroll
        for (int j = 0; j < 2; j++) {
            int li  = tid + j * 256;      // 0..511 over 128 rows x 4 chunks
            int row = li >> 2;
            int ch  = (li & 3) * 8;
            uint32_t da = smem_u32(&As[buf][row][ch]);
            const __nv_bfloat16* sa = g_A + (size_t)(bm + row) * KTOT + k0 + ch;
            int sz = (bm + row < NNODES) ? 16 : 0;
            asm volatile("cp.async.cg.shared.global [%0], [%1], 16, %2;\n"
                         :: "r"(da), "l"(sa), "r"(sz));
            uint32_t db = smem_u32(&Bs[buf][row][ch]);
            const __nv_bfloat16* sb = g_B + (size_t)(bn + row) * KTOT + k0 + ch;
            asm volatile("cp.async.cg.shared.global [%0], [%1], 16;\n"
                         :: "r"(db), "l"(sb));
        }
        asm volatile("cp.async.commit_group;\n");
    };

    auto compute_stage = [&](int buf) {
        #pragma unroll
        for (int kk = 0; kk < BK; kk += 16) {
            uint32_t af[4][4], bf[2][4];
            #pragma unroll
            for (int mi = 0; mi < 4; mi++) {
                uint32_t addr = smem_u32(&As[buf][wm * 64 + mi * 16 + a_r][kk + a_k]);
                asm volatile("ldmatrix.sync.aligned.m8n8.x4.shared.b16 {%0,%1,%2,%3}, [%4];"
                             : "=r"(af[mi][0]), "=r"(af[mi][1]),
                               "=r"(af[mi][2]), "=r"(af[mi][3]) : "r"(addr));
            }
            #pragma unroll
            for (int pi = 0; pi < 2; pi++) {
                uint32_t addr = smem_u32(&Bs[buf][wn * 32 + pi * 16 + b_r][kk + b_k]);
                asm volatile("ldmatrix.sync.aligned.m8n8.x4.shared.b16 {%0,%1,%2,%3}, [%4];"
                             : "=r"(bf[pi][0]), "=r"(bf[pi][1]),
                               "=r"(bf[pi][2]), "=r"(bf[pi][3]) : "r"(addr));
            }
            #pragma unroll
            for (int mi = 0; mi < 4; mi++)
                #pragma unroll
                for (int nb = 0; nb < 4; nb++) {
                    uint32_t bb0 = bf[nb >> 1][(nb & 1) * 2];
                    uint32_t bb1 = bf[nb >> 1][(nb & 1) * 2 + 1];
                    asm volatile(
                        "mma.sync.aligned.m16n8k16.row.col.f32.bf16.bf16.f32 "
                        "{%0,%1,%2,%3}, {%4,%5,%6,%7}, {%8,%9}, {%0,%1,%2,%3};"
                        : "+f"(acc[mi][nb][0]), "+f"(acc[mi][nb][1]),
                          "+f"(acc[mi][nb][2]), "+f"(acc[mi][nb][3])
                        : "r"(af[mi][0]), "r"(af[mi][1]),
                          "r"(af[mi][2]), "r"(af[mi][3]),
                          "r"(bb0), "r"(bb1));
                }
        }
    };

    load_stage(0, 0);
    #pragma unroll 1
    for (int it = 0; it < NIT; it++) {
        if (it + 1 < NIT) {
            load_stage(it + 1, (it + 1) & 1);
            asm volatile("cp.async.wait_group 1;\n" ::: "memory");
        } else {
            asm volatile("cp.async.wait_group 0;\n" ::: "memory");
        }
        __syncthreads();
        compute_stage(it & 1);
        __syncthreads();
    }

    // Epilogue: +b1 (cols < 512, whole tile decided by bn), fp16 store
    const bool addb = (bn < HID);
    const int col0 = bn + wn * 32;
    #pragma unroll
    for (int mi = 0; mi < 4; mi++) {
        #pragma unroll
        for (int nb = 0; nb < 4; nb++) {
            int row = bm + wm * 64 + mi * 16 + (lane >> 2);
            int col = col0 + nb * 8 + (lane & 3) * 2;
            float bx = addb ? __ldg(b1 + col)     : 0.0f;
            float by = addb ? __ldg(b1 + col + 1) : 0.0f;
            if (row < NNODES) {
                __half2 v = __floats2half2_rn(acc[mi][nb][0] + bx,
                                              acc[mi][nb][1] + by);
                *(__half2*)(g_Ch + (size_t)row * NCOLS + col) = v;
            }
            if (row + 8 < NNODES) {
                __half2 v = __floats2half2_rn(acc[mi][nb][2] + bx,
                                              acc[mi][nb][3] + by);
                *(__half2*)(g_Ch + (size_t)(row + 8) * NCOLS + col) = v;
            }
        }
    }
}

// ---------------------------------------------------------------------------
// Edge kernel: one warp per edge (grid-stride). Reads A[r] (1KB fp16) +
// B[c] (1KB fp16), relu-sum against W2 held in registers, OUT=2.
// ---------------------------------------------------------------------------
#define EDGE_BLOCKS 2048

__global__ __launch_bounds__(256)
void edge_kernel(const int* __restrict__ batch_r,
                 const int* __restrict__ batch_c,
                 const float* __restrict__ W2,
                 const float* __restrict__ b2,
                 float* __restrict__ out) {
    const int warp = threadIdx.x >> 5;
    const int lane = threadIdx.x & 31;

    // Each lane owns cols {lane*8..+7} and {(lane+32)*8..+7}; load its W2
    // slice into registers once (amortized over ~31 edges per warp).
    float w0[16], w1[16];
    #pragma unroll
    for (int it = 0; it < 2; it++) {
        int cb = (lane + it * 32) * 8;
        #pragma unroll
        for (int q = 0; q < 2; q++) {
            float4 v0 = __ldg((const float4*)(W2 + cb) + q);
            float4 v1 = __ldg((const float4*)(W2 + HID + cb) + q);
            w0[it * 8 + q * 4 + 0] = v0.x; w0[it * 8 + q * 4 + 1] = v0.y;
            w0[it * 8 + q * 4 + 2] = v0.z; w0[it * 8 + q * 4 + 3] = v0.w;
            w1[it * 8 + q * 4 + 0] = v1.x; w1[it * 8 + q * 4 + 1] = v1.y;
            w1[it * 8 + q * 4 + 2] = v1.z; w1[it * 8 + q * 4 + 3] = v1.w;
        }
    }
    const float bb0 = __ldg(b2);
    const float bb1 = __ldg(b2 + 1);

    const int nwarps = EDGE_BLOCKS * 8;
    for (int e = blockIdx.x * 8 + warp; e < NEDGES; e += nwarps) {
        const int r = batch_r[e];
        const int c = batch_c[e];
        const uint4* pa = (const uint4*)(g_Ch + (size_t)r * NCOLS);
        const uint4* pb = (const uint4*)(g_Ch + (size_t)c * NCOLS + HID);
        uint4 a0 = pa[lane];
        uint4 a1 = pa[lane + 32];
        uint4 v0 = pb[lane];
        uint4 v1 = pb[lane + 32];

        float s0 = 0.f, s1 = 0.f;
        const __half2* ha0 = (const __half2*)&a0;
        const __half2* hb0 = (const __half2*)&v0;
        const __half2* ha1 = (const __half2*)&a1;
        const __half2* hb1 = (const __half2*)&v1;
        #pragma unroll
        for (int p = 0; p < 4; p++) {
            float2 fa = __half22float2(ha0[p]);
            float2 fb = __half22float2(hb0[p]);
            float h0 = fmaxf(fa.x + fb.x, 0.f);
            float h1 = fmaxf(fa.y + fb.y, 0.f);
            s0 = fmaf(h0, w0[p * 2], s0);     s1 = fmaf(h0, w1[p * 2], s1);
            s0 = fmaf(h1, w0[p * 2 + 1], s0); s1 = fmaf(h1, w1[p * 2 + 1], s1);
        }
        #pragma unroll
        for (int p = 0; p < 4; p++) {
            float2 fa = __half22float2(ha1[p]);
            float2 fb = __half22float2(hb1[p]);
            float h0 = fmaxf(fa.x + fb.x, 0.f);
            float h1 = fmaxf(fa.y + fb.y, 0.f);
            s0 = fmaf(h0, w0[8 + p * 2], s0);     s1 = fmaf(h0, w1[8 + p * 2], s1);
            s0 = fmaf(h1, w0[8 + p * 2 + 1], s0); s1 = fmaf(h1, w1[8 + p * 2 + 1], s1);
        }

        #pragma unroll
        for (int off = 16; off > 0; off >>= 1) {
            s0 += __shfl_down_sync(0xffffffff, s0, off);
            s1 += __shfl_down_sync(0xffffffff, s1, off);
        }
        if (lane == 0) {
            float2 o;
            o.x = s0 + bb0;
            o.y = s1 + bb1;
            *(float2*)(out + (size_t)e * OUTC) = o;
        }
    }
}

// ---------------------------------------------------------------------------
// Launch
// ---------------------------------------------------------------------------
extern "C" void kernel_launch(void* const* d_in, const int* in_sizes, int n_in,
                              void* d_out, int out_size) {
    const float* z       = (const float*)d_in[0];
    const int*   batch_r = (const int*)  d_in[1];
    const int*   batch_c = (const int*)  d_in[2];
    const float* W1      = (const float*)d_in[3];
    const float* b1      = (const float*)d_in[4];
    const float* W2      = (const float*)d_in[5];
    const float* b2      = (const float*)d_in[6];
    float* out = (float*)d_out;

    // 1) Split-precision operand prep
    prep_a_kernel<<<(NNODES * 32 + 255) / 256, 256>>>(z);
    prep_b_kernel<<<(NCOLS * 32 + 255) / 256, 256>>>(W1);

    // 2) C = A' @ B'^T (+b1), fp16 out
    dim3 ggrid(NCOLS / BN, (NNODES + BM - 1) / BM);
    gemm_hmma_kernel<<<ggrid, 256>>>(b1);

    // 3) Fused edge decode
    edge_kernel<<<EDGE_BLOCKS, 256>>>(batch_r, batch_c, W2, b2, out);
}

// round 6
// speedup vs baseline: 2.0996x; 1.1971x over previous
#include <cuda_runtime.h>
#include <cuda_fp16.h>
#include <cstdint>

// Problem constants
#define NNODES 100000
#define NEDGES 500000
#define DZ     128
#define HID    512
#define NCOLS  1024     // [A | B] per node
#define OUTC   2
#define KTOT   256      // compensated K: [zh|zl] x [wh|wh]  (fp16)

// Scratch (static device arrays: allocation-free per harness rules)
__device__ __half g_Ch[(size_t)NNODES * NCOLS];   // C = [A|B] in fp16 (205 MB)
__device__ __half g_A[(size_t)NNODES * KTOT];     // A' (51 MB)
__device__ __half g_B[(size_t)NCOLS  * KTOT];     // B' (512 KB)

__device__ __forceinline__ uint32_t smem_u32(const void* p) {
    uint32_t a;
    asm("{ .reg .u64 t; cvta.to.shared.u64 t, %1; cvt.u32.u64 %0, t; }"
        : "=r"(a) : "l"(p));
    return a;
}

// fp16 split: hi = fp16(v), lo = fp16(v - hi)
__device__ __forceinline__ void split_fp16(float4 v, uint2& hi, uint2& lo) {
    float f[4] = {v.x, v.y, v.z, v.w};
    uint16_t h[4], l[4];
    #pragma unroll
    for (int i = 0; i < 4; i++) {
        __half hh = __float2half_rn(f[i]);
        __half ll = __float2half_rn(f[i] - __half2float(hh));
        h[i] = __half_as_ushort(hh);
        l[i] = __half_as_ushort(ll);
    }
    hi.x = (uint32_t)h[0] | ((uint32_t)h[1] << 16);
    hi.y = (uint32_t)h[2] | ((uint32_t)h[3] << 16);
    lo.x = (uint32_t)l[0] | ((uint32_t)l[1] << 16);
    lo.y = (uint32_t)l[2] | ((uint32_t)l[3] << 16);
}

// ---------------------------------------------------------------------------
// Prep A': row m = [zh(128) | zl(128)]   (fp16)
// ---------------------------------------------------------------------------
__global__ __launch_bounds__(256)
void prep_a_kernel(const float* __restrict__ z) {
    int idx = blockIdx.x * blockDim.x + threadIdx.x;   // over NNODES*32 float4s
    if (idx >= NNODES * 32) return;
    int m = idx >> 5;
    int c4 = idx & 31;
    float4 v = __ldg(((const float4*)z) + idx);
    uint2 ph, pl;
    split_fp16(v, ph, pl);
    size_t base = (size_t)m * KTOT + c4 * 4;
    *(uint2*)(g_A + base)       = ph;   // block0: zh
    *(uint2*)(g_A + base + 128) = pl;   // block1: zl
}

// ---------------------------------------------------------------------------
// Prep B': row n (out-col) = [wh(128) | wh(128)]  (fp16)
// n<512: w = W1[n][0:128]; n>=512: w = W1[n-512][128:256]
// ---------------------------------------------------------------------------
__global__ __launch_bounds__(256)
void prep_b_kernel(const float* __restrict__ W1) {
    int idx = blockIdx.x * blockDim.x + threadIdx.x;   // over NCOLS*32
    if (idx >= NCOLS * 32) return;
    int n = idx >> 5;
    int c4 = idx & 31;
    const float4* src = (n < HID)
        ? ((const float4*)W1 + n * 64 + c4)
        : ((const float4*)W1 + (n - HID) * 64 + 32 + c4);
    float4 v = __ldg(src);
    uint2 ph, pl;
    split_fp16(v, ph, pl);
    (void)pl;
    size_t base = (size_t)n * KTOT + c4 * 4;
    *(uint2*)(g_B + base)       = ph;   // block0: wh
    *(uint2*)(g_B + base + 128) = ph;   // block1: wh (pairs with zl)
}

// ---------------------------------------------------------------------------
// HMMA GEMM: C[M,1024] = A'[M,256] @ B'[1024,256]^T  (+ b1 on cols < 512),
// stored fp16. Tile 128x128x32, 256 threads (8 warps, each 64x32),
// mma.m16n8k16 fp16 (fp32 acc), cp.async 2-stage pipeline, ldmatrix loads.
// ---------------------------------------------------------------------------
#define BM 128
#define BN 128
#define BK 32
#define LDA 40       // smem row stride in elems (conflict-free for ldmatrix)
#define NIT (KTOT / BK)   // 8

__global__ __launch_bounds__(256, 2)
void gemm_hmma_kernel(const float* __restrict__ b1) {
    __shared__ __half As[2][BM][LDA];
    __shared__ __half Bs[2][BN][LDA];

    const int tid  = threadIdx.x;
    const int lane = tid & 31;
    const int wid  = tid >> 5;
    const int wm   = wid >> 2;       // 0..1 -> m offset wm*64
    const int wn   = wid & 3;        // 0..3 -> n offset wn*32
    const int bn   = blockIdx.x * BN;   // x = n-tile so concurrent CTAs share A
    const int bm   = blockIdx.y * BM;

    float acc[4][4][4];
    #pragma unroll
    for (int i = 0; i < 4; i++)
        #pragma unroll
        for (int j = 0; j < 4; j++)
            #pragma unroll
            for (int k = 0; k < 4; k++) acc[i][j][k] = 0.0f;

    // per-lane ldmatrix address components
    const int a_r = lane & 15;
    const int a_k = (lane >> 4) * 8;
    const int b_r = (lane & 7) + (lane >> 4) * 8;
    const int b_k = ((lane >> 3) & 1) * 8;

    auto load_stage = [&](int it, int buf) {
        const int k0 = it * BK;
        #pragma unroll
        for (int j = 0; j < 2; j++) {
            int li  = tid + j * 256;      // 0..511 over 128 rows x 4 chunks
            int row = li >> 2;
            int ch  = (li & 3) * 8;
            uint32_t da = smem_u32(&As[buf][row][ch]);
            const __half* sa = g_A + (size_t)(bm + row) * KTOT + k0 + ch;
            int sz = (bm + row < NNODES) ? 16 : 0;
            asm volatile("cp.async.cg.shared.global [%0], [%1], 16, %2;\n"
                         :: "r"(da), "l"(sa), "r"(sz));
            uint32_t db = smem_u32(&Bs[buf][row][ch]);
            const __half* sb = g_B + (size_t)(bn + row) * KTOT + k0 + ch;
            asm volatile("cp.async.cg.shared.global [%0], [%1], 16;\n"
                         :: "r"(db), "l"(sb));
        }
        asm volatile("cp.async.commit_group;\n");
    };

    auto compute_stage = [&](int buf) {
        #pragma unroll
        for (int kk = 0; kk < BK; kk += 16) {
            uint32_t af[4][4], bf[2][4];
            #pragma unroll
            for (int mi = 0; mi < 4; mi++) {
                uint32_t addr = smem_u32(&As[buf][wm * 64 + mi * 16 + a_r][kk + a_k]);
                asm volatile("ldmatrix.sync.aligned.m8n8.x4.shared.b16 {%0,%1,%2,%3}, [%4];"
                             : "=r"(af[mi][0]), "=r"(af[mi][1]),
                               "=r"(af[mi][2]), "=r"(af[mi][3]) : "r"(addr));
            }
            #pragma unroll
            for (int pi = 0; pi < 2; pi++) {
                uint32_t addr = smem_u32(&Bs[buf][wn * 32 + pi * 16 + b_r][kk + b_k]);
                asm volatile("ldmatrix.sync.aligned.m8n8.x4.shared.b16 {%0,%1,%2,%3}, [%4];"
                             : "=r"(bf[pi][0]), "=r"(bf[pi][1]),
                               "=r"(bf[pi][2]), "=r"(bf[pi][3]) : "r"(addr));
            }
            #pragma unroll
            for (int mi = 0; mi < 4; mi++)
                #pragma unroll
                for (int nb = 0; nb < 4; nb++) {
                    uint32_t bb0 = bf[nb >> 1][(nb & 1) * 2];
                    uint32_t bb1 = bf[nb >> 1][(nb & 1) * 2 + 1];
                    asm volatile(
                        "mma.sync.aligned.m16n8k16.row.col.f32.f16.f16.f32 "
                        "{%0,%1,%2,%3}, {%4,%5,%6,%7}, {%8,%9}, {%0,%1,%2,%3};"
                        : "+f"(acc[mi][nb][0]), "+f"(acc[mi][nb][1]),
                          "+f"(acc[mi][nb][2]), "+f"(acc[mi][nb][3])
                        : "r"(af[mi][0]), "r"(af[mi][1]),
                          "r"(af[mi][2]), "r"(af[mi][3]),
                          "r"(bb0), "r"(bb1));
                }
        }
    };

    load_stage(0, 0);
    #pragma unroll 1
    for (int it = 0; it < NIT; it++) {
        if (it + 1 < NIT) {
            load_stage(it + 1, (it + 1) & 1);
            asm volatile("cp.async.wait_group 1;\n" ::: "memory");
        } else {
            asm volatile("cp.async.wait_group 0;\n" ::: "memory");
        }
        __syncthreads();
        compute_stage(it & 1);
        __syncthreads();
    }

    // Epilogue: +b1 (cols < 512, whole tile decided by bn), fp16 store
    const bool addb = (bn < HID);
    const int col0 = bn + wn * 32;
    #pragma unroll
    for (int mi = 0; mi < 4; mi++) {
        #pragma unroll
        for (int nb = 0; nb < 4; nb++) {
            int row = bm + wm * 64 + mi * 16 + (lane >> 2);
            int col = col0 + nb * 8 + (lane & 3) * 2;
            float bx = addb ? __ldg(b1 + col)     : 0.0f;
            float by = addb ? __ldg(b1 + col + 1) : 0.0f;
            if (row < NNODES) {
                __half2 v = __floats2half2_rn(acc[mi][nb][0] + bx,
                                              acc[mi][nb][1] + by);
                *(__half2*)(g_Ch + (size_t)row * NCOLS + col) = v;
            }
            if (row + 8 < NNODES) {
                __half2 v = __floats2half2_rn(acc[mi][nb][2] + bx,
                                              acc[mi][nb][3] + by);
                *(__half2*)(g_Ch + (size_t)(row + 8) * NCOLS + col) = v;
            }
        }
    }
}

// ---------------------------------------------------------------------------
// Edge kernel: one warp per edge (grid-stride). W2 in SMEM (low regs, high
// occupancy). Reads A[r] (1KB fp16) + B[c] (1KB fp16), relu-sum, OUT=2.
// ---------------------------------------------------------------------------
#define EDGE_BLOCKS 2048

__global__ __launch_bounds__(256)
void edge_kernel(const int* __restrict__ batch_r,
                 const int* __restrict__ batch_c,
                 const float* __restrict__ W2,
                 const float* __restrict__ b2,
                 float* __restrict__ out) {
    __shared__ float4 sW0[HID / 4];
    __shared__ float4 sW1[HID / 4];

    const int tid = threadIdx.x;
    if (tid < HID / 4) {
        sW0[tid] = __ldg((const float4*)W2 + tid);
        sW1[tid] = __ldg((const float4*)(W2 + HID) + tid);
    }
    __syncthreads();

    const int warp = tid >> 5;
    const int lane = tid & 31;
    const int gw = blockIdx.x * 8 + warp;
    const int nw = EDGE_BLOCKS * 8;
    const float bb0 = __ldg(b2);
    const float bb1 = __ldg(b2 + 1);

    for (int e = gw; e < NEDGES; e += nw) {
        const int r = batch_r[e];
        const int c = batch_c[e];
        const uint4* pa = (const uint4*)(g_Ch + (size_t)r * NCOLS);
        const uint4* pb = (const uint4*)(g_Ch + (size_t)c * NCOLS + HID);
        // lane owns cols [lane*8, lane*8+8) and [(lane+32)*8, +8)
        uint4 a0 = pa[lane];
        uint4 a1 = pa[lane + 32];
        uint4 v0 = pb[lane];
        uint4 v1 = pb[lane + 32];

        float s0 = 0.f, s1 = 0.f;
        const __half2* ha0 = (const __half2*)&a0;
        const __half2* hb0 = (const __half2*)&v0;
        const __half2* ha1 = (const __half2*)&a1;
        const __half2* hb1 = (const __half2*)&v1;

        #pragma unroll
        for (int q = 0; q < 2; q++) {       // two float4-weight chunks per block
            float4 w0 = sW0[lane * 2 + q];
            float4 w1 = sW1[lane * 2 + q];
            float2 fa = __half22float2(ha0[q * 2]);
            float2 fb = __half22float2(hb0[q * 2]);
            float h0 = fmaxf(fa.x + fb.x, 0.f);
            float h1 = fmaxf(fa.y + fb.y, 0.f);
            fa = __half22float2(ha0[q * 2 + 1]);
            fb = __half22float2(hb0[q * 2 + 1]);
            float h2 = fmaxf(fa.x + fb.x, 0.f);
            float h3 = fmaxf(fa.y + fb.y, 0.f);
            s0 = fmaf(h0, w0.x, s0); s1 = fmaf(h0, w1.x, s1);
            s0 = fmaf(h1, w0.y, s0); s1 = fmaf(h1, w1.y, s1);
            s0 = fmaf(h2, w0.z, s0); s1 = fmaf(h2, w1.z, s1);
            s0 = fmaf(h3, w0.w, s0); s1 = fmaf(h3, w1.w, s1);
        }
        #pragma unroll
        for (int q = 0; q < 2; q++) {
            float4 w0 = sW0[64 + lane * 2 + q];
            float4 w1 = sW1[64 + lane * 2 + q];
            float2 fa = __half22float2(ha1[q * 2]);
            float2 fb = __half22float2(hb1[q * 2]);
            float h0 = fmaxf(fa.x + fb.x, 0.f);
            float h1 = fmaxf(fa.y + fb.y, 0.f);
            fa = __half22float2(ha1[q * 2 + 1]);
            fb = __half22float2(hb1[q * 2 + 1]);
            float h2 = fmaxf(fa.x + fb.x, 0.f);
            float h3 = fmaxf(fa.y + fb.y, 0.f);
            s0 = fmaf(h0, w0.x, s0); s1 = fmaf(h0, w1.x, s1);
            s0 = fmaf(h1, w0.y, s0); s1 = fmaf(h1, w1.y, s1);
            s0 = fmaf(h2, w0.z, s0); s1 = fmaf(h2, w1.z, s1);
            s0 = fmaf(h3, w0.w, s0); s1 = fmaf(h3, w1.w, s1);
        }

        #pragma unroll
        for (int off = 16; off > 0; off >>= 1) {
            s0 += __shfl_down_sync(0xffffffff, s0, off);
            s1 += __shfl_down_sync(0xffffffff, s1, off);
        }
        if (lane == 0) {
            float2 o;
            o.x = s0 + bb0;
            o.y = s1 + bb1;
            *(float2*)(out + (size_t)e * OUTC) = o;
        }
    }
}

// ---------------------------------------------------------------------------
// Launch
// ---------------------------------------------------------------------------
extern "C" void kernel_launch(void* const* d_in, const int* in_sizes, int n_in,
                              void* d_out, int out_size) {
    const float* z       = (const float*)d_in[0];
    const int*   batch_r = (const int*)  d_in[1];
    const int*   batch_c = (const int*)  d_in[2];
    const float* W1      = (const float*)d_in[3];
    const float* b1      = (const float*)d_in[4];
    const float* W2      = (const float*)d_in[5];
    const float* b2      = (const float*)d_in[6];
    float* out = (float*)d_out;

    // 1) Split-precision operand prep
    prep_a_kernel<<<(NNODES * 32 + 255) / 256, 256>>>(z);
    prep_b_kernel<<<(NCOLS * 32 + 255) / 256, 256>>>(W1);

    // 2) C = A' @ B'^T (+b1), fp16 out
    dim3 ggrid(NCOLS / BN, (NNODES + BM - 1) / BM);
    gemm_hmma_kernel<<<ggrid, 256>>>(b1);

    // 3) Fused edge decode
    edge_kernel<<<EDGE_BLOCKS, 256>>>(batch_r, batch_c, W2, b2, out);
}

// round 7
// speedup vs baseline: 2.8254x; 1.3457x over previous
#include <cuda_runtime.h>
#include <cuda_fp16.h>
#include <cstdint>

// Problem constants
#define NNODES 100000
#define NEDGES 500000
#define DZ     128
#define HID    512
#define NCOLS  1024     // [A | B] per node
#define OUTC   2
#define KTOT   128      // plain fp16 K

// Scratch (static device arrays: allocation-free per harness rules)
__device__ __half g_Ch[(size_t)NNODES * NCOLS];   // C = [A|B] in fp16 (205 MB)
__device__ __half g_A[(size_t)NNODES * KTOT];     // z in fp16 (25.6 MB)
__device__ __half g_B[(size_t)NCOLS  * KTOT];     // W1 reshaped, fp16 (256 KB)

__device__ __forceinline__ uint32_t smem_u32(const void* p) {
    uint32_t a;
    asm("{ .reg .u64 t; cvta.to.shared.u64 t, %1; cvt.u32.u64 %0, t; }"
        : "=r"(a) : "l"(p));
    return a;
}

__device__ __forceinline__ uint2 cvt4_fp16(float4 v) {
    uint16_t h[4];
    h[0] = __half_as_ushort(__float2half_rn(v.x));
    h[1] = __half_as_ushort(__float2half_rn(v.y));
    h[2] = __half_as_ushort(__float2half_rn(v.z));
    h[3] = __half_as_ushort(__float2half_rn(v.w));
    uint2 p;
    p.x = (uint32_t)h[0] | ((uint32_t)h[1] << 16);
    p.y = (uint32_t)h[2] | ((uint32_t)h[3] << 16);
    return p;
}

// ---------------------------------------------------------------------------
// Prep A: z -> fp16, row-major [NNODES, 128]
// ---------------------------------------------------------------------------
__global__ __launch_bounds__(256)
void prep_a_kernel(const float* __restrict__ z) {
    int idx = blockIdx.x * blockDim.x + threadIdx.x;   // over NNODES*32 float4s
    if (idx >= NNODES * 32) return;
    float4 v = __ldg(((const float4*)z) + idx);
    *(uint2*)(g_A + (size_t)idx * 4) = cvt4_fp16(v);
}

// ---------------------------------------------------------------------------
// Prep B: row n (out-col) = fp16 of the relevant W1 half-row
// n<512: w = W1[n][0:128]; n>=512: w = W1[n-512][128:256]
// ---------------------------------------------------------------------------
__global__ __launch_bounds__(256)
void prep_b_kernel(const float* __restrict__ W1) {
    int idx = blockIdx.x * blockDim.x + threadIdx.x;   // over NCOLS*32
    if (idx >= NCOLS * 32) return;
    int n = idx >> 5;
    int c4 = idx & 31;
    const float4* src = (n < HID)
        ? ((const float4*)W1 + n * 64 + c4)
        : ((const float4*)W1 + (n - HID) * 64 + 32 + c4);
    float4 v = __ldg(src);
    *(uint2*)(g_B + (size_t)n * KTOT + c4 * 4) = cvt4_fp16(v);
}

// ---------------------------------------------------------------------------
// HMMA GEMM: C[M,1024] = A[M,128] @ B[1024,128]^T  (+ b1 on cols < 512),
// stored fp16. Tile 128x128x32, 256 threads (8 warps, each 64x32),
// mma.m16n8k16 fp16 (fp32 acc), cp.async 2-stage pipeline, ldmatrix loads.
// ---------------------------------------------------------------------------
#define BM 128
#define BN 128
#define BK 32
#define LDA 40       // smem row stride in elems (conflict-free for ldmatrix)
#define NIT (KTOT / BK)   // 4

__global__ __launch_bounds__(256, 2)
void gemm_hmma_kernel(const float* __restrict__ b1) {
    __shared__ __half As[2][BM][LDA];
    __shared__ __half Bs[2][BN][LDA];

    const int tid  = threadIdx.x;
    const int lane = tid & 31;
    const int wid  = tid >> 5;
    const int wm   = wid >> 2;       // 0..1 -> m offset wm*64
    const int wn   = wid & 3;        // 0..3 -> n offset wn*32
    const int bn   = blockIdx.x * BN;   // x = n-tile so concurrent CTAs share A
    const int bm   = blockIdx.y * BM;

    float acc[4][4][4];
    #pragma unroll
    for (int i = 0; i < 4; i++)
        #pragma unroll
        for (int j = 0; j < 4; j++)
            #pragma unroll
            for (int k = 0; k < 4; k++) acc[i][j][k] = 0.0f;

    const int a_r = lane & 15;
    const int a_k = (lane >> 4) * 8;
    const int b_r = (lane & 7) + (lane >> 4) * 8;
    const int b_k = ((lane >> 3) & 1) * 8;

    auto load_stage = [&](int it, int buf) {
        const int k0 = it * BK;
        #pragma unroll
        for (int j = 0; j < 2; j++) {
            int li  = tid + j * 256;      // 0..511 over 128 rows x 4 chunks
            int row = li >> 2;
            int ch  = (li & 3) * 8;
            uint32_t da = smem_u32(&As[buf][row][ch]);
            const __half* sa = g_A + (size_t)(bm + row) * KTOT + k0 + ch;
            int sz = (bm + row < NNODES) ? 16 : 0;
            asm volatile("cp.async.cg.shared.global [%0], [%1], 16, %2;\n"
                         :: "r"(da), "l"(sa), "r"(sz));
            uint32_t db = smem_u32(&Bs[buf][row][ch]);
            const __half* sb = g_B + (size_t)(bn + row) * KTOT + k0 + ch;
            asm volatile("cp.async.cg.shared.global [%0], [%1], 16;\n"
                         :: "r"(db), "l"(sb));
        }
        asm volatile("cp.async.commit_group;\n");
    };

    auto compute_stage = [&](int buf) {
        #pragma unroll
        for (int kk = 0; kk < BK; kk += 16) {
            uint32_t af[4][4], bf[2][4];
            #pragma unroll
            for (int mi = 0; mi < 4; mi++) {
                uint32_t addr = smem_u32(&As[buf][wm * 64 + mi * 16 + a_r][kk + a_k]);
                asm volatile("ldmatrix.sync.aligned.m8n8.x4.shared.b16 {%0,%1,%2,%3}, [%4];"
                             : "=r"(af[mi][0]), "=r"(af[mi][1]),
                               "=r"(af[mi][2]), "=r"(af[mi][3]) : "r"(addr));
            }
            #pragma unroll
            for (int pi = 0; pi < 2; pi++) {
                uint32_t addr = smem_u32(&Bs[buf][wn * 32 + pi * 16 + b_r][kk + b_k]);
                asm volatile("ldmatrix.sync.aligned.m8n8.x4.shared.b16 {%0,%1,%2,%3}, [%4];"
                             : "=r"(bf[pi][0]), "=r"(bf[pi][1]),
                               "=r"(bf[pi][2]), "=r"(bf[pi][3]) : "r"(addr));
            }
            #pragma unroll
            for (int mi = 0; mi < 4; mi++)
                #pragma unroll
                for (int nb = 0; nb < 4; nb++) {
                    uint32_t bb0 = bf[nb >> 1][(nb & 1) * 2];
                    uint32_t bb1 = bf[nb >> 1][(nb & 1) * 2 + 1];
                    asm volatile(
                        "mma.sync.aligned.m16n8k16.row.col.f32.f16.f16.f32 "
                        "{%0,%1,%2,%3}, {%4,%5,%6,%7}, {%8,%9}, {%0,%1,%2,%3};"
                        : "+f"(acc[mi][nb][0]), "+f"(acc[mi][nb][1]),
                          "+f"(acc[mi][nb][2]), "+f"(acc[mi][nb][3])
                        : "r"(af[mi][0]), "r"(af[mi][1]),
                          "r"(af[mi][2]), "r"(af[mi][3]),
                          "r"(bb0), "r"(bb1));
                }
        }
    };

    load_stage(0, 0);
    #pragma unroll 1
    for (int it = 0; it < NIT; it++) {
        if (it + 1 < NIT) {
            load_stage(it + 1, (it + 1) & 1);
            asm volatile("cp.async.wait_group 1;\n" ::: "memory");
        } else {
            asm volatile("cp.async.wait_group 0;\n" ::: "memory");
        }
        __syncthreads();
        compute_stage(it & 1);
        __syncthreads();
    }

    // Epilogue: +b1 (cols < 512, whole tile decided by bn), fp16 store
    const bool addb = (bn < HID);
    const int col0 = bn + wn * 32;
    #pragma unroll
    for (int mi = 0; mi < 4; mi++) {
        #pragma unroll
        for (int nb = 0; nb < 4; nb++) {
            int row = bm + wm * 64 + mi * 16 + (lane >> 2);
            int col = col0 + nb * 8 + (lane & 3) * 2;
            float bx = addb ? __ldg(b1 + col)     : 0.0f;
            float by = addb ? __ldg(b1 + col + 1) : 0.0f;
            if (row < NNODES) {
                __half2 v = __floats2half2_rn(acc[mi][nb][0] + bx,
                                              acc[mi][nb][1] + by);
                *(__half2*)(g_Ch + (size_t)row * NCOLS + col) = v;
            }
            if (row + 8 < NNODES) {
                __half2 v = __floats2half2_rn(acc[mi][nb][2] + bx,
                                              acc[mi][nb][3] + by);
                *(__half2*)(g_Ch + (size_t)(row + 8) * NCOLS + col) = v;
            }
        }
    }
}

// ---------------------------------------------------------------------------
// Edge kernel: one warp per edge, 4-stage cp.async pipeline (HBM->SMEM,
// lane-private slots), W2 in registers. 12 outstanding 16B loads/lane.
// ---------------------------------------------------------------------------
#define EDGE_BLOCKS 2048
#define ESTAGES 4
// per-warp stage buffer: 2KB = 128 uint4 (A half then B half)
#define EDGE_SMEM (8 * ESTAGES * 2048)

__global__ __launch_bounds__(256)
void edge_kernel(const int* __restrict__ batch_r,
                 const int* __restrict__ batch_c,
                 const float* __restrict__ W2,
                 const float* __restrict__ b2,
                 float* __restrict__ out) {
    extern __shared__ uint4 dsm[];    // [8 warps][ESTAGES][128 uint4]

    const int tid  = threadIdx.x;
    const int warp = tid >> 5;
    const int lane = tid & 31;

    // W2 slice in registers (R4 layout): lane owns cols {lane*8..+7} and
    // {(lane+32)*8..+7} for both output rows.
    float w0[16], w1[16];
    #pragma unroll
    for (int it = 0; it < 2; it++) {
        int cb = (lane + it * 32) * 8;
        #pragma unroll
        for (int q = 0; q < 2; q++) {
            float4 v0 = __ldg((const float4*)(W2 + cb) + q);
            float4 v1 = __ldg((const float4*)(W2 + HID + cb) + q);
            w0[it * 8 + q * 4 + 0] = v0.x; w0[it * 8 + q * 4 + 1] = v0.y;
            w0[it * 8 + q * 4 + 2] = v0.z; w0[it * 8 + q * 4 + 3] = v0.w;
            w1[it * 8 + q * 4 + 0] = v1.x; w1[it * 8 + q * 4 + 1] = v1.y;
            w1[it * 8 + q * 4 + 2] = v1.z; w1[it * 8 + q * 4 + 3] = v1.w;
        }
    }
    const float bb0 = __ldg(b2);
    const float bb1 = __ldg(b2 + 1);

    uint4* wbuf = dsm + warp * (ESTAGES * 128);
    const int gw = blockIdx.x * 8 + warp;
    const int nw = EDGE_BLOCKS * 8;

    auto issue = [&](int e, int s) {
        if (e < NEDGES) {
            int r = __ldg(batch_r + e);
            int c = __ldg(batch_c + e);
            const char* pa = (const char*)(g_Ch + (size_t)r * NCOLS);
            const char* pb = (const char*)(g_Ch + (size_t)c * NCOLS + HID);
            uint32_t d = smem_u32(wbuf + s * 128) + lane * 16;
            asm volatile("cp.async.cg.shared.global [%0], [%1], 16;\n"
                         :: "r"(d), "l"(pa + lane * 16));
            asm volatile("cp.async.cg.shared.global [%0], [%1], 16;\n"
                         :: "r"(d + 512), "l"(pa + 512 + lane * 16));
            asm volatile("cp.async.cg.shared.global [%0], [%1], 16;\n"
                         :: "r"(d + 1024), "l"(pb + lane * 16));
            asm volatile("cp.async.cg.shared.global [%0], [%1], 16;\n"
                         :: "r"(d + 1536), "l"(pb + 512 + lane * 16));
        }
        asm volatile("cp.async.commit_group;\n");
    };

    issue(gw, 0);
    issue(gw + nw, 1);
    issue(gw + 2 * nw, 2);

    int s = 0;
    for (int e = gw; e < NEDGES; e += nw) {
        asm volatile("cp.async.wait_group 2;\n" ::: "memory");
        issue(e + 3 * nw, (s + 3) & 3);

        // compute from stage s (lane-private data: written by this lane)
        const uint4* st = wbuf + s * 128;
        uint4 a0 = st[lane];
        uint4 a1 = st[32 + lane];
        uint4 v0 = st[64 + lane];
        uint4 v1 = st[96 + lane];

        float s0 = 0.f, s1 = 0.f;
        const __half2* ha0 = (const __half2*)&a0;
        const __half2* hb0 = (const __half2*)&v0;
        const __half2* ha1 = (const __half2*)&a1;
        const __half2* hb1 = (const __half2*)&v1;
        #pragma unroll
        for (int p = 0; p < 4; p++) {
            float2 fa = __half22float2(ha0[p]);
            float2 fb = __half22float2(hb0[p]);
            float h0 = fmaxf(fa.x + fb.x, 0.f);
            float h1 = fmaxf(fa.y + fb.y, 0.f);
            s0 = fmaf(h0, w0[p * 2], s0);     s1 = fmaf(h0, w1[p * 2], s1);
            s0 = fmaf(h1, w0[p * 2 + 1], s0); s1 = fmaf(h1, w1[p * 2 + 1], s1);
        }
        #pragma unroll
        for (int p = 0; p < 4; p++) {
            float2 fa = __half22float2(ha1[p]);
            float2 fb = __half22float2(hb1[p]);
            float h0 = fmaxf(fa.x + fb.x, 0.f);
            float h1 = fmaxf(fa.y + fb.y, 0.f);
            s0 = fmaf(h0, w0[8 + p * 2], s0);     s1 = fmaf(h0, w1[8 + p * 2], s1);
            s0 = fmaf(h1, w0[8 + p * 2 + 1], s0); s1 = fmaf(h1, w1[8 + p * 2 + 1], s1);
        }

        #pragma unroll
        for (int off = 16; off > 0; off >>= 1) {
            s0 += __shfl_down_sync(0xffffffff, s0, off);
            s1 += __shfl_down_sync(0xffffffff, s1, off);
        }
        if (lane == 0) {
            float2 o;
            o.x = s0 + bb0;
            o.y = s1 + bb1;
            *(float2*)(out + (size_t)e * OUTC) = o;
        }
        s = (s + 1) & 3;
    }
}

// ---------------------------------------------------------------------------
// Launch
// ---------------------------------------------------------------------------
extern "C" void kernel_launch(void* const* d_in, const int* in_sizes, int n_in,
                              void* d_out, int out_size) {
    const float* z       = (const float*)d_in[0];
    const int*   batch_r = (const int*)  d_in[1];
    const int*   batch_c = (const int*)  d_in[2];
    const float* W1      = (const float*)d_in[3];
    const float* b1      = (const float*)d_in[4];
    const float* W2      = (const float*)d_in[5];
    const float* b2      = (const float*)d_in[6];
    float* out = (float*)d_out;

    // Idempotent, capture-safe (host-side attribute, no stream work).
    cudaFuncSetAttribute(edge_kernel,
                         cudaFuncAttributeMaxDynamicSharedMemorySize, EDGE_SMEM);

    // 1) fp16 operand prep
    prep_a_kernel<<<(NNODES * 32 + 255) / 256, 256>>>(z);
    prep_b_kernel<<<(NCOLS * 32 + 255) / 256, 256>>>(W1);

    // 2) C = A @ B^T (+b1), fp16 out
    dim3 ggrid(NCOLS / BN, (NNODES + BM - 1) / BM);
    gemm_hmma_kernel<<<ggrid, 256>>>(b1);

    // 3) Fused edge decode (pipelined gather)
    edge_kernel<<<EDGE_BLOCKS, 256, EDGE_SMEM>>>(batch_r, batch_c, W2, b2, out);
}

// round 8
// speedup vs baseline: 3.5438x; 1.2543x over previous
#include <cuda_runtime.h>
#include <cuda_fp16.h>
#include <cstdint>

// Problem constants
#define NNODES 100000
#define NEDGES 500000
#define DZ     128
#define HID    512
#define NCOLS  1024     // [A | B] per node
#define OUTC   2
#define KTOT   128      // plain fp16 K

// Scratch (static device arrays: allocation-free per harness rules)
__device__ __half g_Ch[(size_t)NNODES * NCOLS];   // C = [A|B] in fp16 (205 MB)
__device__ __half g_A[(size_t)NNODES * KTOT];     // z in fp16 (25.6 MB)
__device__ __half g_B[(size_t)NCOLS  * KTOT];     // W1 reshaped, fp16 (256 KB)

__device__ __forceinline__ uint32_t smem_u32(const void* p) {
    uint32_t a;
    asm("{ .reg .u64 t; cvta.to.shared.u64 t, %1; cvt.u32.u64 %0, t; }"
        : "=r"(a) : "l"(p));
    return a;
}

__device__ __forceinline__ uint2 cvt4_fp16(float4 v) {
    uint16_t h[4];
    h[0] = __half_as_ushort(__float2half_rn(v.x));
    h[1] = __half_as_ushort(__float2half_rn(v.y));
    h[2] = __half_as_ushort(__float2half_rn(v.z));
    h[3] = __half_as_ushort(__float2half_rn(v.w));
    uint2 p;
    p.x = (uint32_t)h[0] | ((uint32_t)h[1] << 16);
    p.y = (uint32_t)h[2] | ((uint32_t)h[3] << 16);
    return p;
}

// ---------------------------------------------------------------------------
// Prep A: z -> fp16, row-major [NNODES, 128]
// ---------------------------------------------------------------------------
__global__ __launch_bounds__(256)
void prep_a_kernel(const float* __restrict__ z) {
    int idx = blockIdx.x * blockDim.x + threadIdx.x;   // over NNODES*32 float4s
    if (idx >= NNODES * 32) return;
    float4 v = __ldg(((const float4*)z) + idx);
    *(uint2*)(g_A + (size_t)idx * 4) = cvt4_fp16(v);
}

// ---------------------------------------------------------------------------
// Prep B: row n (out-col) = fp16 of the relevant W1 half-row
// n<512: w = W1[n][0:128]; n>=512: w = W1[n-512][128:256]
// ---------------------------------------------------------------------------
__global__ __launch_bounds__(256)
void prep_b_kernel(const float* __restrict__ W1) {
    int idx = blockIdx.x * blockDim.x + threadIdx.x;   // over NCOLS*32
    if (idx >= NCOLS * 32) return;
    int n = idx >> 5;
    int c4 = idx & 31;
    const float4* src = (n < HID)
        ? ((const float4*)W1 + n * 64 + c4)
        : ((const float4*)W1 + (n - HID) * 64 + 32 + c4);
    float4 v = __ldg(src);
    *(uint2*)(g_B + (size_t)n * KTOT + c4 * 4) = cvt4_fp16(v);
}

// ---------------------------------------------------------------------------
// HMMA GEMM: C[M,1024] = A[M,128] @ B[1024,128]^T  (+ b1 on cols < 512),
// stored fp16. Tile 128x128x32, 256 threads (8 warps, each 64x32),
// mma.m16n8k16 fp16 (fp32 acc), 4-stage full-K cp.async prefetch,
// SMEM-staged coalesced epilogue.
// ---------------------------------------------------------------------------
#define BM 128
#define BN 128
#define BK 32
#define LDA 40            // smem row stride in halfs (conflict-free ldmatrix)
#define GSTAGE (BM * LDA) // halfs per operand stage = 5120
#define GEMM_SMEM (8 * GSTAGE * 2)   // 4 A-stages + 4 B-stages = 81920 B
#define EPI_LD 136        // epilogue staging row stride (halfs), conflict-free

__global__ __launch_bounds__(256, 2)
void gemm_hmma_kernel(const float* __restrict__ b1) {
    extern __shared__ __half gsm[];
    __half* As = gsm;                 // [4][GSTAGE]
    __half* Bs = gsm + 4 * GSTAGE;    // [4][GSTAGE]

    const int tid  = threadIdx.x;
    const int lane = tid & 31;
    const int wid  = tid >> 5;
    const int wm   = wid >> 2;       // 0..1 -> m offset wm*64
    const int wn   = wid & 3;        // 0..3 -> n offset wn*32
    const int bn   = blockIdx.x * BN;   // x = n-tile so concurrent CTAs share A
    const int bm   = blockIdx.y * BM;

    float acc[4][4][4];
    #pragma unroll
    for (int i = 0; i < 4; i++)
        #pragma unroll
        for (int j = 0; j < 4; j++)
            #pragma unroll
            for (int k = 0; k < 4; k++) acc[i][j][k] = 0.0f;

    const int a_r = lane & 15;
    const int a_k = (lane >> 4) * 8;
    const int b_r = (lane & 7) + (lane >> 4) * 8;
    const int b_k = ((lane >> 3) & 1) * 8;

    auto load_stage = [&](int it, int buf) {
        const int k0 = it * BK;
        #pragma unroll
        for (int j = 0; j < 2; j++) {
            int li  = tid + j * 256;      // 0..511 over 128 rows x 4 chunks
            int row = li >> 2;
            int ch  = (li & 3) * 8;
            uint32_t da = smem_u32(As + buf * GSTAGE + row * LDA + ch);
            const __half* sa = g_A + (size_t)(bm + row) * KTOT + k0 + ch;
            int sz = (bm + row < NNODES) ? 16 : 0;
            asm volatile("cp.async.cg.shared.global [%0], [%1], 16, %2;\n"
                         :: "r"(da), "l"(sa), "r"(sz));
            uint32_t db = smem_u32(Bs + buf * GSTAGE + row * LDA + ch);
            const __half* sb = g_B + (size_t)(bn + row) * KTOT + k0 + ch;
            asm volatile("cp.async.cg.shared.global [%0], [%1], 16;\n"
                         :: "r"(db), "l"(sb));
        }
        asm volatile("cp.async.commit_group;\n");
    };

    auto compute_stage = [&](int buf) {
        const __half* Ab = As + buf * GSTAGE;
        const __half* Bb = Bs + buf * GSTAGE;
        #pragma unroll
        for (int kk = 0; kk < BK; kk += 16) {
            uint32_t af[4][4], bf[2][4];
            #pragma unroll
            for (int mi = 0; mi < 4; mi++) {
                uint32_t addr = smem_u32(Ab + (wm * 64 + mi * 16 + a_r) * LDA + kk + a_k);
                asm volatile("ldmatrix.sync.aligned.m8n8.x4.shared.b16 {%0,%1,%2,%3}, [%4];"
                             : "=r"(af[mi][0]), "=r"(af[mi][1]),
                               "=r"(af[mi][2]), "=r"(af[mi][3]) : "r"(addr));
            }
            #pragma unroll
            for (int pi = 0; pi < 2; pi++) {
                uint32_t addr = smem_u32(Bb + (wn * 32 + pi * 16 + b_r) * LDA + kk + b_k);
                asm volatile("ldmatrix.sync.aligned.m8n8.x4.shared.b16 {%0,%1,%2,%3}, [%4];"
                             : "=r"(bf[pi][0]), "=r"(bf[pi][1]),
                               "=r"(bf[pi][2]), "=r"(bf[pi][3]) : "r"(addr));
            }
            #pragma unroll
            for (int mi = 0; mi < 4; mi++)
                #pragma unroll
                for (int nb = 0; nb < 4; nb++) {
                    uint32_t bb0 = bf[nb >> 1][(nb & 1) * 2];
                    uint32_t bb1 = bf[nb >> 1][(nb & 1) * 2 + 1];
                    asm volatile(
                        "mma.sync.aligned.m16n8k16.row.col.f32.f16.f16.f32 "
                        "{%0,%1,%2,%3}, {%4,%5,%6,%7}, {%8,%9}, {%0,%1,%2,%3};"
                        : "+f"(acc[mi][nb][0]), "+f"(acc[mi][nb][1]),
                          "+f"(acc[mi][nb][2]), "+f"(acc[mi][nb][3])
                        : "r"(af[mi][0]), "r"(af[mi][1]),
                          "r"(af[mi][2]), "r"(af[mi][3]),
                          "r"(bb0), "r"(bb1));
                }
        }
    };

    // full-K prefetch: issue 3 stages up front
    load_stage(0, 0);
    load_stage(1, 1);
    load_stage(2, 2);

    asm volatile("cp.async.wait_group 2;\n" ::: "memory");
    __syncthreads();
    load_stage(3, 3);
    compute_stage(0);

    asm volatile("cp.async.wait_group 2;\n" ::: "memory");
    __syncthreads();
    compute_stage(1);

    asm volatile("cp.async.wait_group 1;\n" ::: "memory");
    __syncthreads();
    compute_stage(2);

    asm volatile("cp.async.wait_group 0;\n" ::: "memory");
    __syncthreads();
    compute_stage(3);

    // ---- Epilogue: acc -> SMEM staging (fp16, +b1) -> coalesced stores ----
    __syncthreads();    // all reads of stage buffers complete before reuse
    __half* cst = gsm;  // [128][EPI_LD]
    const bool addb = (bn < HID);
    const int col0 = wn * 32;
    #pragma unroll
    for (int mi = 0; mi < 4; mi++) {
        #pragma unroll
        for (int nb = 0; nb < 4; nb++) {
            int r0 = wm * 64 + mi * 16 + (lane >> 2);
            int cl = col0 + nb * 8 + (lane & 3) * 2;
            float bx = addb ? __ldg(b1 + bn + cl)     : 0.0f;
            float by = addb ? __ldg(b1 + bn + cl + 1) : 0.0f;
            *(__half2*)(cst + r0 * EPI_LD + cl) =
                __floats2half2_rn(acc[mi][nb][0] + bx, acc[mi][nb][1] + by);
            *(__half2*)(cst + (r0 + 8) * EPI_LD + cl) =
                __floats2half2_rn(acc[mi][nb][2] + bx, acc[mi][nb][3] + by);
        }
    }
    __syncthreads();
    // copy-out: 128 rows x 256B, 16B per thread-chunk, fully coalesced
    #pragma unroll
    for (int i = tid; i < 128 * 16; i += 256) {
        int row = i >> 4;
        int j   = i & 15;
        if (bm + row < NNODES) {
            uint4 v = *(const uint4*)(cst + row * EPI_LD + j * 8);
            *(uint4*)(g_Ch + (size_t)(bm + row) * NCOLS + bn + j * 8) = v;
        }
    }
}

// ---------------------------------------------------------------------------
// Edge kernel: one warp per edge, 3-stage cp.async pipeline (HBM->SMEM,
// lane-private slots), W2 in registers, half2 add+relu.
// ---------------------------------------------------------------------------
#define EDGE_BLOCKS 2048
#define ESTAGES 3
// per-warp stage buffer: 2KB = 128 uint4 (A half then B half)
#define EDGE_SMEM (8 * ESTAGES * 2048)

__global__ __launch_bounds__(256, 4)
void edge_kernel(const int* __restrict__ batch_r,
                 const int* __restrict__ batch_c,
                 const float* __restrict__ W2,
                 const float* __restrict__ b2,
                 float* __restrict__ out) {
    extern __shared__ uint4 dsm[];    // [8 warps][ESTAGES][128 uint4]

    const int tid  = threadIdx.x;
    const int warp = tid >> 5;
    const int lane = tid & 31;

    // W2 slice in registers: lane owns cols {lane*8..+7} and {(lane+32)*8..+7}
    float w0[16], w1[16];
    #pragma unroll
    for (int it = 0; it < 2; it++) {
        int cb = (lane + it * 32) * 8;
        #pragma unroll
        for (int q = 0; q < 2; q++) {
            float4 v0 = __ldg((const float4*)(W2 + cb) + q);
            float4 v1 = __ldg((const float4*)(W2 + HID + cb) + q);
            w0[it * 8 + q * 4 + 0] = v0.x; w0[it * 8 + q * 4 + 1] = v0.y;
            w0[it * 8 + q * 4 + 2] = v0.z; w0[it * 8 + q * 4 + 3] = v0.w;
            w1[it * 8 + q * 4 + 0] = v1.x; w1[it * 8 + q * 4 + 1] = v1.y;
            w1[it * 8 + q * 4 + 2] = v1.z; w1[it * 8 + q * 4 + 3] = v1.w;
        }
    }
    const float bb0 = __ldg(b2);
    const float bb1 = __ldg(b2 + 1);

    uint4* wbuf = dsm + warp * (ESTAGES * 128);
    const int gw = blockIdx.x * 8 + warp;
    const int nw = EDGE_BLOCKS * 8;

    auto issue = [&](int e, int s) {
        if (e < NEDGES) {
            int r = __ldg(batch_r + e);
            int c = __ldg(batch_c + e);
            const char* pa = (const char*)(g_Ch + (size_t)r * NCOLS);
            const char* pb = (const char*)(g_Ch + (size_t)c * NCOLS + HID);
            uint32_t d = smem_u32(wbuf + s * 128) + lane * 16;
            asm volatile("cp.async.cg.shared.global [%0], [%1], 16;\n"
                         :: "r"(d), "l"(pa + lane * 16));
            asm volatile("cp.async.cg.shared.global [%0], [%1], 16;\n"
                         :: "r"(d + 512), "l"(pa + 512 + lane * 16));
            asm volatile("cp.async.cg.shared.global [%0], [%1], 16;\n"
                         :: "r"(d + 1024), "l"(pb + lane * 16));
            asm volatile("cp.async.cg.shared.global [%0], [%1], 16;\n"
                         :: "r"(d + 1536), "l"(pb + 512 + lane * 16));
        }
        asm volatile("cp.async.commit_group;\n");
    };

    issue(gw, 0);
    issue(gw + nw, 1);

    const __half2 zero2 = __float2half2_rn(0.0f);
    int s = 0;
    for (int e = gw; e < NEDGES; e += nw) {
        asm volatile("cp.async.wait_group 1;\n" ::: "memory");
        issue(e + 2 * nw, (s + 2) % ESTAGES);

        const uint4* st = wbuf + s * 128;
        uint4 a0 = st[lane];
        uint4 a1 = st[32 + lane];
        uint4 v0 = st[64 + lane];
        uint4 v1 = st[96 + lane];

        float s0 = 0.f, s1 = 0.f;
        const __half2* ha0 = (const __half2*)&a0;
        const __half2* hb0 = (const __half2*)&v0;
        const __half2* ha1 = (const __half2*)&a1;
        const __half2* hb1 = (const __half2*)&v1;
        #pragma unroll
        for (int p = 0; p < 4; p++) {
            __half2 h = __hmax2(__hadd2(ha0[p], hb0[p]), zero2);
            float2 f = __half22float2(h);
            s0 = fmaf(f.x, w0[p * 2], s0);     s1 = fmaf(f.x, w1[p * 2], s1);
            s0 = fmaf(f.y, w0[p * 2 + 1], s0); s1 = fmaf(f.y, w1[p * 2 + 1], s1);
        }
        #pragma unroll
        for (int p = 0; p < 4; p++) {
            __half2 h = __hmax2(__hadd2(ha1[p], hb1[p]), zero2);
            float2 f = __half22float2(h);
            s0 = fmaf(f.x, w0[8 + p * 2], s0);     s1 = fmaf(f.x, w1[8 + p * 2], s1);
            s0 = fmaf(f.y, w0[8 + p * 2 + 1], s0); s1 = fmaf(f.y, w1[8 + p * 2 + 1], s1);
        }

        #pragma unroll
        for (int off = 16; off > 0; off >>= 1) {
            s0 += __shfl_down_sync(0xffffffff, s0, off);
            s1 += __shfl_down_sync(0xffffffff, s1, off);
        }
        if (lane == 0) {
            float2 o;
            o.x = s0 + bb0;
            o.y = s1 + bb1;
            *(float2*)(out + (size_t)e * OUTC) = o;
        }
        s++;
        if (s == ESTAGES) s = 0;
    }
}

// ---------------------------------------------------------------------------
// Launch
// ---------------------------------------------------------------------------
extern "C" void kernel_launch(void* const* d_in, const int* in_sizes, int n_in,
                              void* d_out, int out_size) {
    const float* z       = (const float*)d_in[0];
    const int*   batch_r = (const int*)  d_in[1];
    const int*   batch_c = (const int*)  d_in[2];
    const float* W1      = (const float*)d_in[3];
    const float* b1      = (const float*)d_in[4];
    const float* W2      = (const float*)d_in[5];
    const float* b2      = (const float*)d_in[6];
    float* out = (float*)d_out;

    // Idempotent, capture-safe host-side attributes.
    cudaFuncSetAttribute(gemm_hmma_kernel,
                         cudaFuncAttributeMaxDynamicSharedMemorySize, GEMM_SMEM);
    cudaFuncSetAttribute(edge_kernel,
                         cudaFuncAttributeMaxDynamicSharedMemorySize, EDGE_SMEM);

    // 1) fp16 operand prep
    prep_a_kernel<<<(NNODES * 32 + 255) / 256, 256>>>(z);
    prep_b_kernel<<<(NCOLS * 32 + 255) / 256, 256>>>(W1);

    // 2) C = A @ B^T (+b1), fp16 out
    dim3 ggrid(NCOLS / BN, (NNODES + BM - 1) / BM);
    gemm_hmma_kernel<<<ggrid, 256, GEMM_SMEM>>>(b1);

    // 3) Fused edge decode (pipelined gather)
    edge_kernel<<<EDGE_BLOCKS, 256, EDGE_SMEM>>>(batch_r, batch_c, W2, b2, out);
}

// round 9
// speedup vs baseline: 3.7421x; 1.0560x over previous
#include <cuda_runtime.h>
#include <cuda_fp16.h>
#include <cstdint>

// Problem constants
#define NNODES 100000
#define NEDGES 500000
#define DZ     128
#define HID    512
#define NCOLS  1024     // [A | B] per node
#define OUTC   2
#define KTOT   128      // plain fp16 K

// Scratch (static device arrays: allocation-free per harness rules)
__device__ __half g_Ch[(size_t)NNODES * NCOLS];   // C = [A|B] in fp16 (205 MB)
__device__ __half g_A[(size_t)NNODES * KTOT];     // z in fp16 (25.6 MB)
__device__ __half g_B[(size_t)NCOLS  * KTOT];     // W1 reshaped, fp16 (256 KB)

__device__ __forceinline__ uint32_t smem_u32(const void* p) {
    uint32_t a;
    asm("{ .reg .u64 t; cvta.to.shared.u64 t, %1; cvt.u32.u64 %0, t; }"
        : "=r"(a) : "l"(p));
    return a;
}

__device__ __forceinline__ uint2 cvt4_fp16(float4 v) {
    uint16_t h[4];
    h[0] = __half_as_ushort(__float2half_rn(v.x));
    h[1] = __half_as_ushort(__float2half_rn(v.y));
    h[2] = __half_as_ushort(__float2half_rn(v.z));
    h[3] = __half_as_ushort(__float2half_rn(v.w));
    uint2 p;
    p.x = (uint32_t)h[0] | ((uint32_t)h[1] << 16);
    p.y = (uint32_t)h[2] | ((uint32_t)h[3] << 16);
    return p;
}

// ---------------------------------------------------------------------------
// Prep A: z -> fp16, row-major [NNODES, 128]
// ---------------------------------------------------------------------------
__global__ __launch_bounds__(256)
void prep_a_kernel(const float* __restrict__ z) {
    int idx = blockIdx.x * blockDim.x + threadIdx.x;   // over NNODES*32 float4s
    if (idx >= NNODES * 32) return;
    float4 v = __ldg(((const float4*)z) + idx);
    *(uint2*)(g_A + (size_t)idx * 4) = cvt4_fp16(v);
}

// ---------------------------------------------------------------------------
// Prep B: row n (out-col) = fp16 of the relevant W1 half-row
// n<512: w = W1[n][0:128]; n>=512: w = W1[n-512][128:256]
// ---------------------------------------------------------------------------
__global__ __launch_bounds__(256)
void prep_b_kernel(const float* __restrict__ W1) {
    int idx = blockIdx.x * blockDim.x + threadIdx.x;   // over NCOLS*32
    if (idx >= NCOLS * 32) return;
    int n = idx >> 5;
    int c4 = idx & 31;
    const float4* src = (n < HID)
        ? ((const float4*)W1 + n * 64 + c4)
        : ((const float4*)W1 + (n - HID) * 64 + 32 + c4);
    float4 v = __ldg(src);
    *(uint2*)(g_B + (size_t)n * KTOT + c4 * 4) = cvt4_fp16(v);
}

// ---------------------------------------------------------------------------
// HMMA GEMM: C[M,1024] = A[M,128] @ B[1024,128]^T  (+ b1 on cols < 512),
// stored fp16. Tile 128x128x32, 256 threads (8 warps, each 64x32),
// mma.m16n8k16 fp16 (fp32 acc), 4-stage full-K cp.async prefetch,
// SMEM-staged coalesced epilogue.  (At legacy-HMMA throughput ceiling.)
// ---------------------------------------------------------------------------
#define BM 128
#define BN 128
#define BK 32
#define LDA 40            // smem row stride in halfs (conflict-free ldmatrix)
#define GSTAGE (BM * LDA) // halfs per operand stage = 5120
#define GEMM_SMEM (8 * GSTAGE * 2)   // 4 A-stages + 4 B-stages = 81920 B
#define EPI_LD 136        // epilogue staging row stride (halfs), conflict-free

__global__ __launch_bounds__(256, 2)
void gemm_hmma_kernel(const float* __restrict__ b1) {
    extern __shared__ __half gsm[];
    __half* As = gsm;                 // [4][GSTAGE]
    __half* Bs = gsm + 4 * GSTAGE;    // [4][GSTAGE]

    const int tid  = threadIdx.x;
    const int lane = tid & 31;
    const int wid  = tid >> 5;
    const int wm   = wid >> 2;       // 0..1 -> m offset wm*64
    const int wn   = wid & 3;        // 0..3 -> n offset wn*32
    const int bn   = blockIdx.x * BN;   // x = n-tile so concurrent CTAs share A
    const int bm   = blockIdx.y * BM;

    float acc[4][4][4];
    #pragma unroll
    for (int i = 0; i < 4; i++)
        #pragma unroll
        for (int j = 0; j < 4; j++)
            #pragma unroll
            for (int k = 0; k < 4; k++) acc[i][j][k] = 0.0f;

    const int a_r = lane & 15;
    const int a_k = (lane >> 4) * 8;
    const int b_r = (lane & 7) + (lane >> 4) * 8;
    const int b_k = ((lane >> 3) & 1) * 8;

    auto load_stage = [&](int it, int buf) {
        const int k0 = it * BK;
        #pragma unroll
        for (int j = 0; j < 2; j++) {
            int li  = tid + j * 256;      // 0..511 over 128 rows x 4 chunks
            int row = li >> 2;
            int ch  = (li & 3) * 8;
            uint32_t da = smem_u32(As + buf * GSTAGE + row * LDA + ch);
            const __half* sa = g_A + (size_t)(bm + row) * KTOT + k0 + ch;
            int sz = (bm + row < NNODES) ? 16 : 0;
            asm volatile("cp.async.cg.shared.global [%0], [%1], 16, %2;\n"
                         :: "r"(da), "l"(sa), "r"(sz));
            uint32_t db = smem_u32(Bs + buf * GSTAGE + row * LDA + ch);
            const __half* sb = g_B + (size_t)(bn + row) * KTOT + k0 + ch;
            asm volatile("cp.async.cg.shared.global [%0], [%1], 16;\n"
                         :: "r"(db), "l"(sb));
        }
        asm volatile("cp.async.commit_group;\n");
    };

    auto compute_stage = [&](int buf) {
        const __half* Ab = As + buf * GSTAGE;
        const __half* Bb = Bs + buf * GSTAGE;
        #pragma unroll
        for (int kk = 0; kk < BK; kk += 16) {
            uint32_t af[4][4], bf[2][4];
            #pragma unroll
            for (int mi = 0; mi < 4; mi++) {
                uint32_t addr = smem_u32(Ab + (wm * 64 + mi * 16 + a_r) * LDA + kk + a_k);
                asm volatile("ldmatrix.sync.aligned.m8n8.x4.shared.b16 {%0,%1,%2,%3}, [%4];"
                             : "=r"(af[mi][0]), "=r"(af[mi][1]),
                               "=r"(af[mi][2]), "=r"(af[mi][3]) : "r"(addr));
            }
            #pragma unroll
            for (int pi = 0; pi < 2; pi++) {
                uint32_t addr = smem_u32(Bb + (wn * 32 + pi * 16 + b_r) * LDA + kk + b_k);
                asm volatile("ldmatrix.sync.aligned.m8n8.x4.shared.b16 {%0,%1,%2,%3}, [%4];"
                             : "=r"(bf[pi][0]), "=r"(bf[pi][1]),
                               "=r"(bf[pi][2]), "=r"(bf[pi][3]) : "r"(addr));
            }
            #pragma unroll
            for (int mi = 0; mi < 4; mi++)
                #pragma unroll
                for (int nb = 0; nb < 4; nb++) {
                    uint32_t bb0 = bf[nb >> 1][(nb & 1) * 2];
                    uint32_t bb1 = bf[nb >> 1][(nb & 1) * 2 + 1];
                    asm volatile(
                        "mma.sync.aligned.m16n8k16.row.col.f32.f16.f16.f32 "
                        "{%0,%1,%2,%3}, {%4,%5,%6,%7}, {%8,%9}, {%0,%1,%2,%3};"
                        : "+f"(acc[mi][nb][0]), "+f"(acc[mi][nb][1]),
                          "+f"(acc[mi][nb][2]), "+f"(acc[mi][nb][3])
                        : "r"(af[mi][0]), "r"(af[mi][1]),
                          "r"(af[mi][2]), "r"(af[mi][3]),
                          "r"(bb0), "r"(bb1));
                }
        }
    };

    // full-K prefetch: issue 3 stages up front
    load_stage(0, 0);
    load_stage(1, 1);
    load_stage(2, 2);

    asm volatile("cp.async.wait_group 2;\n" ::: "memory");
    __syncthreads();
    load_stage(3, 3);
    compute_stage(0);

    asm volatile("cp.async.wait_group 2;\n" ::: "memory");
    __syncthreads();
    compute_stage(1);

    asm volatile("cp.async.wait_group 1;\n" ::: "memory");
    __syncthreads();
    compute_stage(2);

    asm volatile("cp.async.wait_group 0;\n" ::: "memory");
    __syncthreads();
    compute_stage(3);

    // ---- Epilogue: acc -> SMEM staging (fp16, +b1) -> coalesced stores ----
    __syncthreads();    // all reads of stage buffers complete before reuse
    __half* cst = gsm;  // [128][EPI_LD]
    const bool addb = (bn < HID);
    const int col0 = wn * 32;
    #pragma unroll
    for (int mi = 0; mi < 4; mi++) {
        #pragma unroll
        for (int nb = 0; nb < 4; nb++) {
            int r0 = wm * 64 + mi * 16 + (lane >> 2);
            int cl = col0 + nb * 8 + (lane & 3) * 2;
            float bx = addb ? __ldg(b1 + bn + cl)     : 0.0f;
            float by = addb ? __ldg(b1 + bn + cl + 1) : 0.0f;
            *(__half2*)(cst + r0 * EPI_LD + cl) =
                __floats2half2_rn(acc[mi][nb][0] + bx, acc[mi][nb][1] + by);
            *(__half2*)(cst + (r0 + 8) * EPI_LD + cl) =
                __floats2half2_rn(acc[mi][nb][2] + bx, acc[mi][nb][3] + by);
        }
    }
    __syncthreads();
    // copy-out: 128 rows x 256B, 16B per thread-chunk, fully coalesced
    #pragma unroll
    for (int i = tid; i < 128 * 16; i += 256) {
        int row = i >> 4;
        int j   = i & 15;
        if (bm + row < NNODES) {
            uint4 v = *(const uint4*)(cst + row * EPI_LD + j * 8);
            *(uint4*)(g_Ch + (size_t)(bm + row) * NCOLS + bn + j * 8) = v;
        }
    }
}

// ---------------------------------------------------------------------------
// Edge kernel: one warp per edge, 3-stage cp.async pipeline (HBM->SMEM,
// lane-private slots), W2 in registers, half2 add+relu.
// 192-thread CTAs (6 warps) -> 36KB smem/CTA -> 6 CTAs/SM resident.
// ---------------------------------------------------------------------------
#define EDGE_WPB 6
#define EDGE_BLOCKS 2664     // 3 exact waves at 148 SM x 6 CTAs
#define ESTAGES 3
// per-warp stage buffer: 2KB = 128 uint4 (A half then B half)
#define EDGE_SMEM (EDGE_WPB * ESTAGES * 2048)

__global__ __launch_bounds__(EDGE_WPB * 32, 6)
void edge_kernel(const int* __restrict__ batch_r,
                 const int* __restrict__ batch_c,
                 const float* __restrict__ W2,
                 const float* __restrict__ b2,
                 float* __restrict__ out) {
    extern __shared__ uint4 dsm[];    // [EDGE_WPB warps][ESTAGES][128 uint4]

    const int tid  = threadIdx.x;
    const int warp = tid >> 5;
    const int lane = tid & 31;

    // W2 slice in registers: lane owns cols {lane*8..+7} and {(lane+32)*8..+7}
    float w0[16], w1[16];
    #pragma unroll
    for (int it = 0; it < 2; it++) {
        int cb = (lane + it * 32) * 8;
        #pragma unroll
        for (int q = 0; q < 2; q++) {
            float4 v0 = __ldg((const float4*)(W2 + cb) + q);
            float4 v1 = __ldg((const float4*)(W2 + HID + cb) + q);
            w0[it * 8 + q * 4 + 0] = v0.x; w0[it * 8 + q * 4 + 1] = v0.y;
            w0[it * 8 + q * 4 + 2] = v0.z; w0[it * 8 + q * 4 + 3] = v0.w;
            w1[it * 8 + q * 4 + 0] = v1.x; w1[it * 8 + q * 4 + 1] = v1.y;
            w1[it * 8 + q * 4 + 2] = v1.z; w1[it * 8 + q * 4 + 3] = v1.w;
        }
    }
    const float bb0 = __ldg(b2);
    const float bb1 = __ldg(b2 + 1);

    uint4* wbuf = dsm + warp * (ESTAGES * 128);
    const int gw = blockIdx.x * EDGE_WPB + warp;
    const int nw = EDGE_BLOCKS * EDGE_WPB;

    auto issue = [&](int e, int s) {
        if (e < NEDGES) {
            int r = __ldg(batch_r + e);
            int c = __ldg(batch_c + e);
            const char* pa = (const char*)(g_Ch + (size_t)r * NCOLS);
            const char* pb = (const char*)(g_Ch + (size_t)c * NCOLS + HID);
            uint32_t d = smem_u32(wbuf + s * 128) + lane * 16;
            asm volatile("cp.async.cg.shared.global [%0], [%1], 16;\n"
                         :: "r"(d), "l"(pa + lane * 16));
            asm volatile("cp.async.cg.shared.global [%0], [%1], 16;\n"
                         :: "r"(d + 512), "l"(pa + 512 + lane * 16));
            asm volatile("cp.async.cg.shared.global [%0], [%1], 16;\n"
                         :: "r"(d + 1024), "l"(pb + lane * 16));
            asm volatile("cp.async.cg.shared.global [%0], [%1], 16;\n"
                         :: "r"(d + 1536), "l"(pb + 512 + lane * 16));
        }
        asm volatile("cp.async.commit_group;\n");
    };

    issue(gw, 0);
    issue(gw + nw, 1);

    const __half2 zero2 = __float2half2_rn(0.0f);
    int s = 0;
    for (int e = gw; e < NEDGES; e += nw) {
        asm volatile("cp.async.wait_group 1;\n" ::: "memory");
        issue(e + 2 * nw, (s + 2) % ESTAGES);

        const uint4* st = wbuf + s * 128;
        uint4 a0 = st[lane];
        uint4 a1 = st[32 + lane];
        uint4 v0 = st[64 + lane];
        uint4 v1 = st[96 + lane];

        float s0 = 0.f, s1 = 0.f;
        const __half2* ha0 = (const __half2*)&a0;
        const __half2* hb0 = (const __half2*)&v0;
        const __half2* ha1 = (const __half2*)&a1;
        const __half2* hb1 = (const __half2*)&v1;
        #pragma unroll
        for (int p = 0; p < 4; p++) {
            __half2 h = __hmax2(__hadd2(ha0[p], hb0[p]), zero2);
            float2 f = __half22float2(h);
            s0 = fmaf(f.x, w0[p * 2], s0);     s1 = fmaf(f.x, w1[p * 2], s1);
            s0 = fmaf(f.y, w0[p * 2 + 1], s0); s1 = fmaf(f.y, w1[p * 2 + 1], s1);
        }
        #pragma unroll
        for (int p = 0; p < 4; p++) {
            __half2 h = __hmax2(__hadd2(ha1[p], hb1[p]), zero2);
            float2 f = __half22float2(h);
            s0 = fmaf(f.x, w0[8 + p * 2], s0);     s1 = fmaf(f.x, w1[8 + p * 2], s1);
            s0 = fmaf(f.y, w0[8 + p * 2 + 1], s0); s1 = fmaf(f.y, w1[8 + p * 2 + 1], s1);
        }

        #pragma unroll
        for (int off = 16; off > 0; off >>= 1) {
            s0 += __shfl_down_sync(0xffffffff, s0, off);
            s1 += __shfl_down_sync(0xffffffff, s1, off);
        }
        if (lane == 0) {
            float2 o;
            o.x = s0 + bb0;
            o.y = s1 + bb1;
            *(float2*)(out + (size_t)e * OUTC) = o;
        }
        s++;
        if (s == ESTAGES) s = 0;
    }
}

// ---------------------------------------------------------------------------
// Launch
// ---------------------------------------------------------------------------
extern "C" void kernel_launch(void* const* d_in, const int* in_sizes, int n_in,
                              void* d_out, int out_size) {
    const float* z       = (const float*)d_in[0];
    const int*   batch_r = (const int*)  d_in[1];
    const int*   batch_c = (const int*)  d_in[2];
    const float* W1      = (const float*)d_in[3];
    const float* b1      = (const float*)d_in[4];
    const float* W2      = (const float*)d_in[5];
    const float* b2      = (const float*)d_in[6];
    float* out = (float*)d_out;

    // Idempotent, capture-safe host-side attributes.
    cudaFuncSetAttribute(gemm_hmma_kernel,
                         cudaFuncAttributeMaxDynamicSharedMemorySize, GEMM_SMEM);
    cudaFuncSetAttribute(edge_kernel,
                         cudaFuncAttributeMaxDynamicSharedMemorySize, EDGE_SMEM);

    // 1) fp16 operand prep
    prep_a_kernel<<<(NNODES * 32 + 255) / 256, 256>>>(z);
    prep_b_kernel<<<(NCOLS * 32 + 255) / 256, 256>>>(W1);

    // 2) C = A @ B^T (+b1), fp16 out
    dim3 ggrid(NCOLS / BN, (NNODES + BM - 1) / BM);
    gemm_hmma_kernel<<<ggrid, 256, GEMM_SMEM>>>(b1);

    // 3) Fused edge decode (pipelined gather)
    edge_kernel<<<EDGE_BLOCKS, EDGE_WPB * 32, EDGE_SMEM>>>(batch_r, batch_c, W2, b2, out);
}